// round 6
// baseline (speedup 1.0000x reference)
#include <cuda_runtime.h>

// Problem constants (from reference config)
#define BB 2
#define NN 6
#define DD 48
#define FH 16
#define FW 44
#define CC 80
#define NX 256
#define NY 256

#define NCHUNK (CC/4)                 // 20 float4 chunks per point
#define NGROUP (BB*NN*DD*FW)          // 25344 (b,n,d,w) groups
#define NTHREAD (NGROUP*NCHUNK)       // 506880
#define TPB 256

__device__ __forceinline__ void inv3(const float* m, float* o) {
    float a = m[0], b = m[1], c = m[2];
    float d = m[3], e = m[4], f = m[5];
    float g = m[6], h = m[7], i = m[8];
    float A = e * i - f * h;
    float B = -(d * i - f * g);
    float Cc = d * h - e * g;
    float det = a * A + b * B + c * Cc;
    float id = 1.0f / det;
    o[0] = A * id;
    o[1] = -(b * i - c * h) * id;
    o[2] = (b * f - c * e) * id;
    o[3] = B * id;
    o[4] = (a * i - c * g) * id;
    o[5] = -(a * f - c * d) * id;
    o[6] = Cc * id;
    o[7] = -(a * h - b * g) * id;
    o[8] = (a * e - b * d) * id;
}

__global__ void __launch_bounds__(TPB, 6)
pool_kernel(const float* __restrict__ x,
            const float* __restrict__ rots,
            const float* __restrict__ trans,
            const float* __restrict__ intrins,
            const float* __restrict__ post_rots,
            const float* __restrict__ post_trans,
            float* __restrict__ out) {
    int g = blockIdx.x * TPB + threadIdx.x;
    if (g >= NTHREAD) return;

    int chunk = g % NCHUNK;
    int grp = g / NCHUNK;
    int w = grp % FW;
    int rem = grp / FW;
    int d = rem % DD;
    int cam = rem / DD;
    int b = cam / NN;

    // ---- per-thread camera-derived params (redundant across 20 chunks; cheap) ----
    float invK[9], invP[9], comb[9];
    inv3(intrins + cam * 9, invK);
    inv3(post_rots + cam * 9, invP);
    {
        const float* R = rots + cam * 9;
        #pragma unroll
        for (int i = 0; i < 3; i++)
            #pragma unroll
            for (int k = 0; k < 3; k++)
                comb[i * 3 + k] = R[i * 3 + 0] * invK[0 * 3 + k]
                                + R[i * 3 + 1] * invK[1 * 3 + k]
                                + R[i * 3 + 2] * invK[2 * 3 + k];
    }
    float t0 = trans[cam * 3 + 0], t1 = trans[cam * 3 + 1], t2 = trans[cam * 3 + 2];
    float pt0 = post_trans[cam * 3 + 0], pt1 = post_trans[cam * 3 + 1], pt2 = post_trans[cam * 3 + 2];

    float u = (float)w * (703.0f / 43.0f);       // linspace(0, 703, 44)
    float dep = 2.0f + (float)d * (56.0f / 48.0f);

    // base (h=0) and per-h step of q = invP @ (frustum - post_trans); v = 17*h
    float a0 = u - pt0, a2 = dep - pt2;
    float qb0 = invP[0] * a0 + invP[1] * (-pt1) + invP[2] * a2;
    float qb1 = invP[3] * a0 + invP[4] * (-pt1) + invP[5] * a2;
    float qb2 = invP[6] * a0 + invP[7] * (-pt1) + invP[8] * a2;
    float qs0 = invP[1] * 17.0f, qs1 = invP[4] * 17.0f, qs2 = invP[7] * 17.0f;

    // ---- classification pass: uniform / all-dropped / mixed (registers only) ----
    int first = -2;
    bool uniform = true;
    bool anyvalid = false;
    #pragma unroll
    for (int h = 0; h < FH; h++) {
        float fh = (float)h;
        float q0 = qb0 + fh * qs0;
        float q1 = qb1 + fh * qs1;
        float q2 = qb2 + fh * qs2;
        float r0 = q0 * q2, r1 = q1 * q2, r2 = q2;
        float ex = comb[0] * r0 + comb[1] * r1 + comb[2] * r2 + t0;
        float ey = comb[3] * r0 + comb[4] * r1 + comb[5] * r2 + t1;
        float ez = comb[6] * r0 + comb[7] * r1 + comb[8] * r2 + t2;
        int gx = (int)((ex + 51.2f) / 0.4f);     // trunc-toward-zero == astype(int32)
        int gy = (int)((ey + 51.2f) / 0.4f);
        int gz = (int)((ez + 10.0f) / 20.0f);
        bool kept = (gx >= 0) & (gx < NX) & (gy >= 0) & (gy < NY) & (gz == 0);
        int vox = kept ? (gy * NX + gx) : -1;
        if (h == 0) first = vox;
        else uniform &= (vox == first);
        anyvalid |= kept;
    }
    if (!anyvalid) return;                       // no loads, no atomics

    const float* xp = x + (((size_t)(cam * DD + d) * FH * FW + w) * CC) + chunk * 4;
    const int hstride = FW * CC;                 // 3520 floats
    float* obase = out + (size_t)(b * CC + chunk * 4) * (NY * NX);

    if (uniform & (first >= 0)) {
        // dominant case: branch-free, 16 independent streaming loads (MLP=16)
        float4 acc = make_float4(0.f, 0.f, 0.f, 0.f);
        #pragma unroll
        for (int h = 0; h < FH; h++) {
            float4 val = __ldcs(reinterpret_cast<const float4*>(xp + h * hstride));
            acc.x += val.x;
            acc.y += val.y;
            acc.z += val.z;
            acc.w += val.w;
        }
        float* o = obase + first;
        atomicAdd(o, acc.x);
        atomicAdd(o + NY * NX, acc.y);
        atomicAdd(o + 2 * NY * NX, acc.z);
        atomicAdd(o + 3 * NY * NX, acc.w);
        return;
    }

    // mixed column (rare): recompute geometry per h, run-length accumulate
    float4 acc = make_float4(0.f, 0.f, 0.f, 0.f);
    int cur = -1;
    #pragma unroll 1
    for (int h = 0; h < FH; h++) {
        float fh = (float)h;
        float q0 = qb0 + fh * qs0;
        float q1 = qb1 + fh * qs1;
        float q2 = qb2 + fh * qs2;
        float r0 = q0 * q2, r1 = q1 * q2, r2 = q2;
        float ex = comb[0] * r0 + comb[1] * r1 + comb[2] * r2 + t0;
        float ey = comb[3] * r0 + comb[4] * r1 + comb[5] * r2 + t1;
        float ez = comb[6] * r0 + comb[7] * r1 + comb[8] * r2 + t2;
        int gx = (int)((ex + 51.2f) / 0.4f);
        int gy = (int)((ey + 51.2f) / 0.4f);
        int gz = (int)((ez + 10.0f) / 20.0f);
        bool kept = (gx >= 0) & (gx < NX) & (gy >= 0) & (gy < NY) & (gz == 0);
        if (kept) {
            int vox = gy * NX + gx;
            if (vox != cur) {
                if (cur >= 0) {
                    float* o = obase + cur;
                    atomicAdd(o, acc.x);
                    atomicAdd(o + NY * NX, acc.y);
                    atomicAdd(o + 2 * NY * NX, acc.z);
                    atomicAdd(o + 3 * NY * NX, acc.w);
                }
                acc = make_float4(0.f, 0.f, 0.f, 0.f);
                cur = vox;
            }
            float4 val = __ldcs(reinterpret_cast<const float4*>(xp + h * hstride));
            acc.x += val.x;
            acc.y += val.y;
            acc.z += val.z;
            acc.w += val.w;
        }
    }
    if (cur >= 0) {
        float* o = obase + cur;
        atomicAdd(o, acc.x);
        atomicAdd(o + NY * NX, acc.y);
        atomicAdd(o + 2 * NY * NX, acc.z);
        atomicAdd(o + 3 * NY * NX, acc.w);
    }
}

extern "C" void kernel_launch(void* const* d_in, const int* in_sizes, int n_in,
                              void* d_out, int out_size) {
    const float* x          = (const float*)d_in[0];
    const float* rots       = (const float*)d_in[1];
    const float* trans      = (const float*)d_in[2];
    const float* intrins    = (const float*)d_in[3];
    const float* post_rots  = (const float*)d_in[4];
    const float* post_trans = (const float*)d_in[5];
    float* out = (float*)d_out;

    cudaMemsetAsync(out, 0, (size_t)out_size * sizeof(float));

    pool_kernel<<<(NTHREAD + TPB - 1) / TPB, TPB>>>(x, rots, trans, intrins, post_rots,
                                                    post_trans, out);
}

// round 8
// speedup vs baseline: 1.2187x; 1.2187x over previous
#include <cuda_runtime.h>

// Problem constants (from reference config)
#define BB 2
#define NN 6
#define DD 48
#define FH 16
#define FW 44
#define CC 80
#define NX 256
#define NY 256

#define NCHUNK (CC/4)                 // 20 float4 chunks per point
#define NGROUP (BB*NN*DD*FW)          // 25344 (b,n,d,w) groups
#define NTHREAD (NGROUP*NCHUNK)       // 506880
#define TPB 256
#define PLANE (NY*NX)                 // 65536

// per-group classification: >=0 uniform voxel, -1 all dropped, -2 mixed
__device__ int g_cls[NGROUP];
__device__ int g_svox[NGROUP][FH];    // per-h voxel, written only for mixed groups

__device__ __forceinline__ void inv3(const float* m, float* o) {
    float a = m[0], b = m[1], c = m[2];
    float d = m[3], e = m[4], f = m[5];
    float g = m[6], h = m[7], i = m[8];
    float A = e * i - f * h;
    float B = -(d * i - f * g);
    float Cc = d * h - e * g;
    float det = a * A + b * B + c * Cc;
    float id = 1.0f / det;
    o[0] = A * id;
    o[1] = -(b * i - c * h) * id;
    o[2] = (b * f - c * e) * id;
    o[3] = B * id;
    o[4] = (a * i - c * g) * id;
    o[5] = -(a * f - c * d) * id;
    o[6] = Cc * id;
    o[7] = -(a * h - b * g) * id;
    o[8] = (a * e - b * d) * id;
}

// Fused: zero the output (bandwidth-bound) + per-group geometry (hidden under it)
__global__ void __launch_bounds__(TPB)
prep_kernel(float4* __restrict__ out4, int n4,
            const float* __restrict__ rots,
            const float* __restrict__ trans,
            const float* __restrict__ intrins,
            const float* __restrict__ post_rots,
            const float* __restrict__ post_trans) {
    int t = blockIdx.x * TPB + threadIdx.x;
    if (t < n4) out4[t] = make_float4(0.f, 0.f, 0.f, 0.f);

    if (t >= NGROUP) return;
    int grp = t;
    int w = grp % FW;
    int rem = grp / FW;
    int d = rem % DD;
    int cam = rem / DD;

    float invK[9], invP[9], comb[9];
    inv3(intrins + cam * 9, invK);
    inv3(post_rots + cam * 9, invP);
    {
        const float* R = rots + cam * 9;
        #pragma unroll
        for (int i = 0; i < 3; i++)
            #pragma unroll
            for (int k = 0; k < 3; k++)
                comb[i * 3 + k] = R[i * 3 + 0] * invK[0 * 3 + k]
                                + R[i * 3 + 1] * invK[1 * 3 + k]
                                + R[i * 3 + 2] * invK[2 * 3 + k];
    }
    float t0 = trans[cam * 3 + 0], t1 = trans[cam * 3 + 1], t2 = trans[cam * 3 + 2];
    float pt0 = post_trans[cam * 3 + 0], pt1 = post_trans[cam * 3 + 1], pt2 = post_trans[cam * 3 + 2];

    float u = (float)w * (703.0f / 43.0f);       // linspace(0, 703, 44)
    float dep = 2.0f + (float)d * (56.0f / 48.0f);

    int vox[FH];
    #pragma unroll
    for (int h = 0; h < FH; h++) {
        float v = (float)h * 17.0f;              // linspace(0, 255, 16)
        float a0 = u - pt0, a1 = v - pt1, a2 = dep - pt2;
        float q0 = invP[0] * a0 + invP[1] * a1 + invP[2] * a2;
        float q1 = invP[3] * a0 + invP[4] * a1 + invP[5] * a2;
        float q2 = invP[6] * a0 + invP[7] * a1 + invP[8] * a2;
        float r0 = q0 * q2, r1 = q1 * q2, r2 = q2;
        float ex = comb[0] * r0 + comb[1] * r1 + comb[2] * r2 + t0;
        float ey = comb[3] * r0 + comb[4] * r1 + comb[5] * r2 + t1;
        float ez = comb[6] * r0 + comb[7] * r1 + comb[8] * r2 + t2;
        int gx = (int)((ex + 51.2f) / 0.4f);     // trunc-toward-zero == astype(int32)
        int gy = (int)((ey + 51.2f) / 0.4f);
        int gz = (int)((ez + 10.0f) / 20.0f);
        bool kept = (gx >= 0) & (gx < NX) & (gy >= 0) & (gy < NY) & (gz == 0);
        vox[h] = kept ? (gy * NX + gx) : -1;
    }

    int first = vox[0];
    bool uniform = true;
    bool anyvalid = false;
    #pragma unroll
    for (int h = 0; h < FH; h++) {
        uniform &= (vox[h] == first);
        anyvalid |= (vox[h] >= 0);
    }

    int cls;
    if (!anyvalid) cls = -1;
    else if (uniform && first >= 0) cls = first;
    else {
        cls = -2;
        #pragma unroll
        for (int h = 0; h < FH; h++) g_svox[grp][h] = vox[h];
    }
    g_cls[grp] = cls;
}

// Lean pool: 1 broadcast class load -> 16 branch-free loads -> 4 REDs
__global__ void __launch_bounds__(TPB, 6)
pool_kernel(const float* __restrict__ x, float* __restrict__ out) {
    int g = blockIdx.x * TPB + threadIdx.x;

    int chunk = g % NCHUNK;
    int grp = g / NCHUNK;
    int cls = g_cls[grp];
    if (cls == -1) return;                       // whole column dropped

    int gd = grp / FW;                           // cam*DD + d
    int w = grp - gd * FW;
    int b = grp / (NN * DD * FW);

    const float* xp = x + (((size_t)gd * FH * FW + w) * CC) + chunk * 4;
    const int hstride = FW * CC;                 // 3520 floats
    float* obase = out + (size_t)(b * CC + chunk * 4) * PLANE;

    if (cls >= 0) {
        // dominant case: branch-free, 16 independent streaming loads
        float4 acc = make_float4(0.f, 0.f, 0.f, 0.f);
        #pragma unroll
        for (int h = 0; h < FH; h++) {
            float4 val = __ldcs(reinterpret_cast<const float4*>(xp + h * hstride));
            acc.x += val.x;
            acc.y += val.y;
            acc.z += val.z;
            acc.w += val.w;
        }
        float* o = obase + cls;
        atomicAdd(o, acc.x);
        atomicAdd(o + PLANE, acc.y);
        atomicAdd(o + 2 * PLANE, acc.z);
        atomicAdd(o + 3 * PLANE, acc.w);
        return;
    }

    // mixed column (rare): run-length accumulate using per-h table
    float4 acc = make_float4(0.f, 0.f, 0.f, 0.f);
    int cur = -1;
    #pragma unroll 1
    for (int h = 0; h < FH; h++) {
        int vox = g_svox[grp][h];
        if (vox >= 0) {
            if (vox != cur) {
                if (cur >= 0) {
                    float* o = obase + cur;
                    atomicAdd(o, acc.x);
                    atomicAdd(o + PLANE, acc.y);
                    atomicAdd(o + 2 * PLANE, acc.z);
                    atomicAdd(o + 3 * PLANE, acc.w);
                }
                acc = make_float4(0.f, 0.f, 0.f, 0.f);
                cur = vox;
            }
            float4 val = __ldcs(reinterpret_cast<const float4*>(xp + h * hstride));
            acc.x += val.x;
            acc.y += val.y;
            acc.z += val.z;
            acc.w += val.w;
        }
    }
    if (cur >= 0) {
        float* o = obase + cur;
        atomicAdd(o, acc.x);
        atomicAdd(o + PLANE, acc.y);
        atomicAdd(o + 2 * PLANE, acc.z);
        atomicAdd(o + 3 * PLANE, acc.w);
    }
}

extern "C" void kernel_launch(void* const* d_in, const int* in_sizes, int n_in,
                              void* d_out, int out_size) {
    const float* x          = (const float*)d_in[0];
    const float* rots       = (const float*)d_in[1];
    const float* trans      = (const float*)d_in[2];
    const float* intrins    = (const float*)d_in[3];
    const float* post_rots  = (const float*)d_in[4];
    const float* post_trans = (const float*)d_in[5];
    float* out = (float*)d_out;

    int n4 = out_size / 4;
    prep_kernel<<<(n4 + TPB - 1) / TPB, TPB>>>((float4*)out, n4, rots, trans,
                                               intrins, post_rots, post_trans);

    pool_kernel<<<NTHREAD / TPB, TPB>>>(x, out);
}